// round 9
// baseline (speedup 1.0000x reference)
#include <cuda_runtime.h>
#include <cuda_bf16.h>
#include <cuda_fp16.h>
#include <math.h>
#include <stdint.h>

#define S_LEN 2048
#define H_DIM 4096
#define NHQ   32
#define NKVH  8
#define DHEAD 128
#define QKV_N 6144
#define K_IN  4096
#define K3    (3*K_IN)   // 12288
#define WINSZ 1024

// ---------------- scratch ----------------------------------------------------
__device__ float g_qkv[S_LEN * QKV_N];
__device__ float g_cos[S_LEN * 64];
__device__ float g_sin[S_LEN * 64];
__device__ __nv_bfloat16 g_A1[(size_t)S_LEN * K3];
__device__ __nv_bfloat16 g_B1[(size_t)QKV_N * K3];
__device__ __nv_bfloat16 g_A2[(size_t)S_LEN * K3];
__device__ __nv_bfloat16 g_B2[(size_t)H_DIM * K3];

// ---------------- helpers ---------------------------------------------------
__device__ __forceinline__ uint32_t smem_u32(const void* p) {
    uint32_t a;
    asm("{ .reg .u64 t; cvta.to.shared.u64 t, %1; cvt.u32.u64 %0, t; }" : "=r"(a) : "l"(p));
    return a;
}
__device__ __forceinline__ void cpa16(uint32_t dst, const void* src) {
    asm volatile("cp.async.cg.shared.global [%0], [%1], 16;" :: "r"(dst), "l"(src) : "memory");
}
__device__ __forceinline__ uint32_t swz(uint32_t x) { return x ^ ((x >> 3) & 0x70); }

__device__ __forceinline__ void ldmx4(uint32_t* r, uint32_t addr) {
    asm volatile("ldmatrix.sync.aligned.m8n8.x4.shared.b16 {%0,%1,%2,%3}, [%4];"
        : "=r"(r[0]), "=r"(r[1]), "=r"(r[2]), "=r"(r[3]) : "r"(addr));
}
__device__ __forceinline__ void ldmx4t(uint32_t* r, uint32_t addr) {
    asm volatile("ldmatrix.sync.aligned.m8n8.x4.trans.shared.b16 {%0,%1,%2,%3}, [%4];"
        : "=r"(r[0]), "=r"(r[1]), "=r"(r[2]), "=r"(r[3]) : "r"(addr));
}
__device__ __forceinline__ void mma16816(float* c, const uint32_t* a, uint32_t b0, uint32_t b1) {
    asm volatile("mma.sync.aligned.m16n8k16.row.col.f32.bf16.bf16.f32 "
        "{%0,%1,%2,%3}, {%4,%5,%6,%7}, {%8,%9}, {%0,%1,%2,%3};"
        : "+f"(c[0]), "+f"(c[1]), "+f"(c[2]), "+f"(c[3])
        : "r"(a[0]), "r"(a[1]), "r"(a[2]), "r"(a[3]), "r"(b0), "r"(b1));
}
__device__ __forceinline__ void mma16816h(float* c, const uint32_t* a, uint32_t b0, uint32_t b1) {
    asm volatile("mma.sync.aligned.m16n8k16.row.col.f32.f16.f16.f32 "
        "{%0,%1,%2,%3}, {%4,%5,%6,%7}, {%8,%9}, {%0,%1,%2,%3};"
        : "+f"(c[0]), "+f"(c[1]), "+f"(c[2]), "+f"(c[3])
        : "r"(a[0]), "r"(a[1]), "r"(a[2]), "r"(a[3]), "r"(b0), "r"(b1));
}
__device__ __forceinline__ uint32_t pack_h2(float x, float y) {
    __half2 h = __floats2half2_rn(x, y);
    return *(uint32_t*)&h;
}

// ============================================================================
// bf16x3 split conversions (unchanged)
// ============================================================================
__global__ __launch_bounds__(256) void split_a_kernel(
    const float* __restrict__ X, __nv_bfloat16* __restrict__ A, int M)
{
    int idx = blockIdx.x * 256 + threadIdx.x;
    int total = M * (K_IN / 4);
    if (idx >= total) return;
    int m = idx / (K_IN / 4);
    int k = (idx % (K_IN / 4)) * 4;
    float4 v = ((const float4*)X)[idx];
    __nv_bfloat16 h0 = __float2bfloat16_rn(v.x), h1 = __float2bfloat16_rn(v.y);
    __nv_bfloat16 h2 = __float2bfloat16_rn(v.z), h3 = __float2bfloat16_rn(v.w);
    __nv_bfloat16 l0 = __float2bfloat16_rn(v.x - __bfloat162float(h0));
    __nv_bfloat16 l1 = __float2bfloat16_rn(v.y - __bfloat162float(h1));
    __nv_bfloat16 l2 = __float2bfloat16_rn(v.z - __bfloat162float(h2));
    __nv_bfloat16 l3 = __float2bfloat16_rn(v.w - __bfloat162float(h3));
    __nv_bfloat162 H0 = __halves2bfloat162(h0, h1), H1 = __halves2bfloat162(h2, h3);
    __nv_bfloat162 L0 = __halves2bfloat162(l0, l1), L1 = __halves2bfloat162(l2, l3);
    __nv_bfloat16* row = A + (size_t)m * K3;
    *(__nv_bfloat162*)(row + k)              = H0; *(__nv_bfloat162*)(row + k + 2)              = H1;
    *(__nv_bfloat162*)(row + K_IN + k)       = H0; *(__nv_bfloat162*)(row + K_IN + k + 2)       = H1;
    *(__nv_bfloat162*)(row + 2 * K_IN + k)   = L0; *(__nv_bfloat162*)(row + 2 * K_IN + k + 2)   = L1;
}

__global__ __launch_bounds__(256) void split_bT_kernel(
    const float* __restrict__ W, __nv_bfloat16* __restrict__ B, int N)
{
    __shared__ float tl[32][33];
    int n0 = blockIdx.x * 32, k0 = blockIdx.y * 32;
    int tx = threadIdx.x, ty = threadIdx.y;
#pragma unroll
    for (int i = 0; i < 4; i++)
        tl[ty + i * 8][tx] = W[(size_t)(k0 + ty + i * 8) * N + n0 + tx];
    __syncthreads();
#pragma unroll
    for (int i = 0; i < 4; i++) {
        int n = ty + i * 8;
        float x = tl[tx][n];
        __nv_bfloat16 h = __float2bfloat16_rn(x);
        __nv_bfloat16 l = __float2bfloat16_rn(x - __bfloat162float(h));
        __nv_bfloat16* row = B + (size_t)(n0 + n) * K3 + k0 + tx;
        row[0]        = h;
        row[K_IN]     = l;
        row[2 * K_IN] = h;
    }
}

// ============================================================================
// HMMA GEMM (unchanged from R7)
// ============================================================================
#define NSTG 4
#define A_STAGE 32768
#define CHUNK_BYTES 49152
#define SMEM_MM (NSTG * CHUNK_BYTES)
#define NCHUNK (K3 / 64)

__global__ __launch_bounds__(256, 1) void mm_bf16_kernel(
    const __nv_bfloat16* __restrict__ Abf, const __nv_bfloat16* __restrict__ Bbf,
    float* __restrict__ C, int N)
{
    extern __shared__ char smc[];
    const uint32_t sb = smem_u32(smc);
    const char* Ab = (const char*)Abf;
    const char* Bb = (const char*)Bbf;
    const int t = threadIdx.x, lane = t & 31, wid = t >> 5;
    const int bm = blockIdx.y << 8;
    const int bn = blockIdx.x << 7;
    const size_t rowB = (size_t)K3 * 2;

    const int wm = (wid & 3) << 6;
    const int wn = (wid >> 2) << 6;
    const int lr = ((lane >> 3) & 1) * 8 + (lane & 7);
    const int lk = ((lane >> 4) & 1) * 16;

    float acc[4][8][4];
#pragma unroll
    for (int mt = 0; mt < 4; mt++)
#pragma unroll
        for (int nt = 0; nt < 8; nt++)
#pragma unroll
            for (int e = 0; e < 4; e++) acc[mt][nt][e] = 0.f;

#pragma unroll
    for (int c = 0; c < 3; c++) {
        uint32_t aB = sb + c * CHUNK_BYTES;
        uint32_t bB = aB + A_STAGE;
        int kByte = c * 128;
#pragma unroll
        for (int j = 0; j < 8; j++) {
            int idx = t + j * 256; int r = idx >> 3, cc = idx & 7;
            cpa16(aB + swz(r * 128 + cc * 16), Ab + (size_t)(bm + r) * rowB + kByte + cc * 16);
        }
#pragma unroll
        for (int j = 0; j < 4; j++) {
            int idx = t + j * 256; int r = idx >> 3, cc = idx & 7;
            cpa16(bB + swz(r * 128 + cc * 16), Bb + (size_t)(bn + r) * rowB + kByte + cc * 16);
        }
        asm volatile("cp.async.commit_group;" ::: "memory");
    }

    for (int i = 0; i < NCHUNK; i++) {
        asm volatile("cp.async.wait_group 2;" ::: "memory");
        __syncthreads();

        const int pc = i + 3;
        if (pc < NCHUNK) {
            uint32_t aB = sb + (pc & 3) * CHUNK_BYTES;
            uint32_t bB = aB + A_STAGE;
            int kByte = pc * 128;
#pragma unroll
            for (int j = 0; j < 8; j++) {
                int idx = t + j * 256; int r = idx >> 3, cc = idx & 7;
                cpa16(aB + swz(r * 128 + cc * 16), Ab + (size_t)(bm + r) * rowB + kByte + cc * 16);
            }
#pragma unroll
            for (int j = 0; j < 4; j++) {
                int idx = t + j * 256; int r = idx >> 3, cc = idx & 7;
                cpa16(bB + swz(r * 128 + cc * 16), Bb + (size_t)(bn + r) * rowB + kByte + cc * 16);
            }
        }
        asm volatile("cp.async.commit_group;" ::: "memory");

        const uint32_t aB = sb + (i & 3) * CHUNK_BYTES;
        const uint32_t bB = aB + A_STAGE;
#pragma unroll
        for (int ks = 0; ks < 4; ks++) {
            uint32_t ra[4][4], rb[4][4];
            const int kOff = ks * 32 + lk;
#pragma unroll
            for (int mt = 0; mt < 4; mt++)
                ldmx4(ra[mt], aB + swz((wm + mt * 16 + lr) * 128 + kOff));
#pragma unroll
            for (int ng = 0; ng < 4; ng++)
                ldmx4(rb[ng], bB + swz((wn + ng * 16 + lr) * 128 + kOff));
#pragma unroll
            for (int mt = 0; mt < 4; mt++)
#pragma unroll
                for (int ng = 0; ng < 4; ng++) {
                    mma16816(acc[mt][ng * 2],     ra[mt], rb[ng][0], rb[ng][2]);
                    mma16816(acc[mt][ng * 2 + 1], ra[mt], rb[ng][1], rb[ng][3]);
                }
        }
    }

#pragma unroll
    for (int mt = 0; mt < 4; mt++) {
#pragma unroll
        for (int nt = 0; nt < 8; nt++) {
            int row = bm + wm + mt * 16 + (lane >> 2);
            int col = bn + wn + nt * 8 + (lane & 3) * 2;
            *(float2*)(C + (size_t)row * N + col)       = make_float2(acc[mt][nt][0], acc[mt][nt][1]);
            *(float2*)(C + (size_t)(row + 8) * N + col) = make_float2(acc[mt][nt][2], acc[mt][nt][3]);
        }
    }
}

// ============================================================================
// RoPE (unchanged)
// ============================================================================
__global__ void rope_table_kernel(const int* __restrict__ positions)
{
    int idx = blockIdx.x * blockDim.x + threadIdx.x;
    if (idx >= S_LEN * 64) return;
    int s = idx >> 6, i = idx & 63;
    double inv = pow(10000.0, -((double)i) / 64.0);
    double f   = (double)positions[s] * inv;
    g_cos[idx] = (float)cos(f);
    g_sin[idx] = (float)sin(f);
}

__global__ __launch_bounds__(256) void rope_apply_kernel()
{
    int s = blockIdx.x;
    float* base = g_qkv + (size_t)s * QKV_N;
    for (int idx = threadIdx.x; idx < 40 * 64; idx += 256) {
        int hh = idx >> 6, i = idx & 63;
        int off = (hh < 32) ? hh * 128 : 4096 + (hh - 32) * 128;
        float c  = g_cos[(s << 6) + i];
        float sn = g_sin[(s << 6) + i];
        float a = base[off + i];
        float b = base[off + 64 + i];
        base[off + i]      = a * c - b * sn;
        base[off + 64 + i] = b * c + a * sn;
    }
}

// ============================================================================
// Flash attention, P = 1 + E identity.
// P·V = rowsum_fp32(V) + E·Vh, PLUS for tiles containing masked entries an
// exact correction M·Vl (M = -1 masked / 0 valid): without it the masked
// entries leave a +v_low residual (this was R8's 7e-4 error). Vl is staged
// into the K buffer after the S-MMAs (K is dead there) — smem stays 50.5KB.
// ============================================================================
#define ATTN_SMEM 51712
#define RS_PART   49152
#define RS_FINAL  51200

__global__ __launch_bounds__(128, 3) void attn_mma_kernel()
{
    extern __shared__ char smA[];
    const uint32_t sb = smem_u32(smA);
    const uint32_t sQ = sb, sK = sb + 16384, sVh = sb + 32768;

    const int t = threadIdx.x, lane = t & 31, w = t >> 5;
    const int q0 = blockIdx.x << 6;
    const int h  = blockIdx.y;
    const int kvh = h >> 2;
    const float* qb = g_qkv + h * 128;
    const float* kb = g_qkv + 4096 + kvh * 128;
    const float* vb = g_qkv + 5120 + kvh * 128;
    const float scale = 0.08838834764831845f;

    for (int idx = t; idx < 2048; idx += 128) {
        int r = idx >> 5, d4 = idx & 31;
        float4 v = *(const float4*)(qb + (size_t)(q0 + r) * QKV_N + d4 * 4);
        int hf = d4 >> 4, dpr = (d4 & 15) * 4;
        uint2 u;
        u.x = pack_h2(v.x, v.y);
        u.y = pack_h2(v.z, v.w);
        *(uint2*)(smA + hf * 8192 + swz(r * 128 + dpr * 2)) = u;
    }

    const int lr = ((lane >> 3) & 1) * 8 + (lane & 7);
    const int lc = (lane >> 4) * 16;
    const int r0 = lane >> 2;
    const int c2 = (lane & 3) * 2;

    float l_i[2] = {0.f, 0.f};
    float of[16][4];
#pragma unroll
    for (int dd = 0; dd < 16; dd++)
#pragma unroll
        for (int e = 0; e < 4; e++) of[dd][e] = 0.f;

    int lo = q0 - (WINSZ - 1);
    if (lo < 0) lo = 0;
    lo &= ~63;

    const int qi0 = q0 + w * 16 + r0;
    const int qi1 = qi0 + 8;

    for (int j0 = lo; j0 < q0 + 64; j0 += 64) {
        // any (qi,kj) masked in this tile? causal: only diagonal tile;
        // window: only when the tile straddles the window edge.
        const bool hasMask = (j0 == q0) || (q0 + 63 - j0 >= WINSZ);

        __syncthreads();   // previous tile's smem reads complete
        // ---- K tile ----
        for (int idx = t; idx < 2048; idx += 128) {
            int r = idx >> 5, d4 = idx & 31;
            float4 v = *(const float4*)(kb + (size_t)(j0 + r) * QKV_N + d4 * 4);
            int hf = d4 >> 4, dpr = (d4 & 15) * 4;
            uint2 u;
            u.x = pack_h2(v.x, v.y);
            u.y = pack_h2(v.z, v.w);
            *(uint2*)(smA + 16384 + hf * 8192 + swz(r * 128 + dpr * 2)) = u;
        }
        // ---- V tile (Vh) + fp32 partial row-sums ----
        {
            float prs0 = 0.f, prs1 = 0.f, prs2 = 0.f, prs3 = 0.f;
            const int d4 = t & 31;
            const int hf = d4 >> 4, dpr = (d4 & 15) * 4;
#pragma unroll
            for (int i = 0; i < 16; i++) {
                int j = (t >> 5) + i * 4;
                float4 v = *(const float4*)(vb + (size_t)(j0 + j) * QKV_N + d4 * 4);
                uint2 uh;
                uh.x = pack_h2(v.x, v.y);
                uh.y = pack_h2(v.z, v.w);
                *(uint2*)(smA + 32768 + (hf << 13) + swz(j * 128 + dpr * 2)) = uh;
                prs0 += v.x; prs1 += v.y; prs2 += v.z; prs3 += v.w;
            }
            *(float4*)(smA + RS_PART + ((t >> 5) * 128 + d4 * 4) * 4) =
                make_float4(prs0, prs1, prs2, prs3);
        }
        __syncthreads();
        {
            const float* sP = (const float*)(smA + RS_PART);
            float rsum = sP[t] + sP[128 + t] + sP[256 + t] + sP[384 + t];
            *(float*)(smA + RS_FINAL + t * 4) = rsum;
        }
        __syncthreads();

        // ---- S = Q K^T ----
        float sf[8][4];
#pragma unroll
        for (int f = 0; f < 8; f++)
#pragma unroll
            for (int e = 0; e < 4; e++) sf[f][e] = 0.f;

#pragma unroll
        for (int ks = 0; ks < 8; ks++) {
            const int hf = ks >> 2;
            const int kOff = (ks & 3) * 32 + lc;
            uint32_t ra[4];
            ldmx4(ra, sQ + hf * 8192 + swz((w * 16 + lr) * 128 + kOff));
#pragma unroll
            for (int jb = 0; jb < 4; jb++) {
                uint32_t rb[4];
                ldmx4(rb, sK + hf * 8192 + swz((jb * 16 + lr) * 128 + kOff));
                mma16816h(sf[jb * 2],     ra, rb[0], rb[2]);
                mma16816h(sf[jb * 2 + 1], ra, rb[1], rb[3]);
            }
        }

        // ---- masked tiles: stage Vl into the (now dead) K buffer ----
        if (hasMask) {
            __syncthreads();   // all warps finished reading K
            for (int idx = t; idx < 2048; idx += 128) {
                int j = idx >> 5, d4 = idx & 31;
                float4 v = *(const float4*)(vb + (size_t)(j0 + j) * QKV_N + d4 * 4);
                int hf = d4 >> 4, dpr = (d4 & 15) * 4;
                __half h0 = __float2half_rn(v.x), h1 = __float2half_rn(v.y);
                __half h2 = __float2half_rn(v.z), h3 = __float2half_rn(v.w);
                uint2 ul;
                ul.x = pack_h2(v.x - __half2float(h0), v.y - __half2float(h1));
                ul.y = pack_h2(v.z - __half2float(h2), v.w - __half2float(h3));
                *(uint2*)(smA + 16384 + (hf << 13) + swz(j * 128 + dpr * 2)) = ul;
            }
            __syncthreads();
        }

        // ---- eps = p - 1 (masked: -1 exact) + row-sums of eps ----
        float rs0 = 0.f, rs1 = 0.f;
#pragma unroll
        for (int f = 0; f < 8; f++) {
            int kj = j0 + f * 8 + c2;
#pragma unroll
            for (int e = 0; e < 2; e++) {
                int kje = kj + e;
                bool ok0 = (kje <= qi0) && ((qi0 - kje) < WINSZ);
                bool ok1 = (kje <= qi1) && ((qi1 - kje) < WINSZ);
                float e0 = ok0 ? (__expf(sf[f][e] * scale)     - 1.f) : -1.f;
                float e1 = ok1 ? (__expf(sf[f][e + 2] * scale) - 1.f) : -1.f;
                sf[f][e] = e0; sf[f][e + 2] = e1;
                rs0 += e0; rs1 += e1;
            }
        }
        rs0 += __shfl_xor_sync(0xffffffffu, rs0, 1);
        rs0 += __shfl_xor_sync(0xffffffffu, rs0, 2);
        rs1 += __shfl_xor_sync(0xffffffffu, rs1, 1);
        rs1 += __shfl_xor_sync(0xffffffffu, rs1, 2);
        l_i[0] += 64.f + rs0;
        l_i[1] += 64.f + rs1;

        // ---- O += rowsum(V) + E·Vh (+ M·Vl on masked tiles) ----
        const float* rsF = (const float*)(smA + RS_FINAL);
#pragma unroll
        for (int dd = 0; dd < 16; dd++) {
            float ra = rsF[dd * 8 + c2];
            float rb = rsF[dd * 8 + c2 + 1];
            of[dd][0] += ra; of[dd][1] += rb;
            of[dd][2] += ra; of[dd][3] += rb;
        }
#pragma unroll
        for (int kk = 0; kk < 4; kk++) {
            uint32_t aE[4], aM[4];
#pragma unroll
            for (int g = 0; g < 2; g++) {
                int f = kk * 2 + g;
                aE[g * 2]     = pack_h2(sf[f][0], sf[f][1]);
                aE[g * 2 + 1] = pack_h2(sf[f][2], sf[f][3]);
                if (hasMask) {
                    int kj = j0 + f * 8 + c2;
                    float m00 = ((kj     <= qi0) && ((qi0 - kj)     < WINSZ)) ? 0.f : -1.f;
                    float m01 = ((kj + 1 <= qi0) && ((qi0 - kj - 1) < WINSZ)) ? 0.f : -1.f;
                    float m10 = ((kj     <= qi1) && ((qi1 - kj)     < WINSZ)) ? 0.f : -1.f;
                    float m11 = ((kj + 1 <= qi1) && ((qi1 - kj - 1) < WINSZ)) ? 0.f : -1.f;
                    aM[g * 2]     = pack_h2(m00, m01);
                    aM[g * 2 + 1] = pack_h2(m10, m11);
                }
            }
#pragma unroll
            for (int db = 0; db < 8; db++) {
                const int hf = db >> 2;
                const int dloc = (db & 3) * 16;
                uint32_t addr = (hf << 13) + swz((kk * 16 + lr) * 128 + dloc * 2 + lc);
                uint32_t vh[4];
                ldmx4t(vh, sVh + addr);
                mma16816h(of[db * 2],     aE, vh[0], vh[1]);
                mma16816h(of[db * 2 + 1], aE, vh[2], vh[3]);
                if (hasMask) {
                    uint32_t vl[4];
                    ldmx4t(vl, sK + addr);
                    mma16816h(of[db * 2],     aM, vl[0], vl[1]);
                    mma16816h(of[db * 2 + 1], aM, vl[2], vl[3]);
                }
            }
        }
    }

    // ---- epilogue: normalize + bf16x3 split directly into A2 ----
    float inv0 = 1.f / l_i[0], inv1 = 1.f / l_i[1];
    __nv_bfloat16* rowA0 = g_A2 + (size_t)(q0 + w * 16 + r0) * K3 + h * 128;
    __nv_bfloat16* rowA1 = g_A2 + (size_t)(q0 + w * 16 + r0 + 8) * K3 + h * 128;
#pragma unroll
    for (int dd = 0; dd < 16; dd++) {
        int d = dd * 8 + c2;
        float x0 = of[dd][0] * inv0, x1 = of[dd][1] * inv0;
        float y0 = of[dd][2] * inv1, y1 = of[dd][3] * inv1;
        __nv_bfloat16 xh0 = __float2bfloat16_rn(x0), xh1 = __float2bfloat16_rn(x1);
        __nv_bfloat16 yh0 = __float2bfloat16_rn(y0), yh1 = __float2bfloat16_rn(y1);
        __nv_bfloat162 XH = __halves2bfloat162(xh0, xh1);
        __nv_bfloat162 YH = __halves2bfloat162(yh0, yh1);
        __nv_bfloat162 XL = __halves2bfloat162(
            __float2bfloat16_rn(x0 - __bfloat162float(xh0)),
            __float2bfloat16_rn(x1 - __bfloat162float(xh1)));
        __nv_bfloat162 YL = __halves2bfloat162(
            __float2bfloat16_rn(y0 - __bfloat162float(yh0)),
            __float2bfloat16_rn(y1 - __bfloat162float(yh1)));
        *(__nv_bfloat162*)(rowA0 + d)            = XH;
        *(__nv_bfloat162*)(rowA0 + d + K_IN)     = XH;
        *(__nv_bfloat162*)(rowA0 + d + 2 * K_IN) = XL;
        *(__nv_bfloat162*)(rowA1 + d)            = YH;
        *(__nv_bfloat162*)(rowA1 + d + K_IN)     = YH;
        *(__nv_bfloat162*)(rowA1 + d + 2 * K_IN) = YL;
    }
}

// ============================================================================
// launch
// ============================================================================
extern "C" void kernel_launch(void* const* d_in, const int* in_sizes, int n_in,
                              void* d_out, int out_size)
{
    const int*   positions = (const int*)d_in[0];
    const float* hidden    = (const float*)d_in[1];
    const float* w_qkv     = (const float*)d_in[2];
    const float* w_o       = (const float*)d_in[3];
    float*       out       = (float*)d_out;

    float* qkv;
    __nv_bfloat16 *A1, *B1, *A2, *B2;
    cudaGetSymbolAddress((void**)&qkv, g_qkv);
    cudaGetSymbolAddress((void**)&A1, g_A1);
    cudaGetSymbolAddress((void**)&B1, g_B1);
    cudaGetSymbolAddress((void**)&A2, g_A2);
    cudaGetSymbolAddress((void**)&B2, g_B2);

    cudaFuncSetAttribute(mm_bf16_kernel, cudaFuncAttributeMaxDynamicSharedMemorySize, SMEM_MM);
    cudaFuncSetAttribute(attn_mma_kernel, cudaFuncAttributeMaxDynamicSharedMemorySize, ATTN_SMEM);

    rope_table_kernel<<<(S_LEN * 64 + 255) / 256, 256>>>(positions);

    split_a_kernel<<<(S_LEN * (K_IN / 4) + 255) / 256, 256>>>(hidden, A1, S_LEN);
    split_bT_kernel<<<dim3(QKV_N / 32, K_IN / 32), dim3(32, 8)>>>(w_qkv, B1, QKV_N);
    split_bT_kernel<<<dim3(H_DIM / 32, K_IN / 32), dim3(32, 8)>>>(w_o, B2, H_DIM);

    mm_bf16_kernel<<<dim3(QKV_N / 128, S_LEN / 256), 256, SMEM_MM>>>(A1, B1, qkv, QKV_N);

    rope_apply_kernel<<<S_LEN, 256>>>();

    attn_mma_kernel<<<dim3(S_LEN / 64, NHQ), 128, ATTN_SMEM>>>();

    mm_bf16_kernel<<<dim3(H_DIM / 128, S_LEN / 256), 256, SMEM_MM>>>(A2, B2, out, H_DIM);
}

// round 10
// speedup vs baseline: 1.0412x; 1.0412x over previous
#include <cuda_runtime.h>
#include <cuda_bf16.h>
#include <cuda_fp16.h>
#include <math.h>
#include <stdint.h>

#define S_LEN 2048
#define H_DIM 4096
#define NHQ   32
#define NKVH  8
#define DHEAD 128
#define QKV_N 6144
#define K_IN  4096
#define K2    (2*K_IN)   // 8192: [Ah|Al] / [Bh|Bl]
#define WINSZ 1024

// ---------------- scratch ----------------------------------------------------
__device__ float g_qkv[S_LEN * QKV_N];
__device__ float g_cos[S_LEN * 64];
__device__ float g_sin[S_LEN * 64];
__device__ __nv_bfloat16 g_A1[(size_t)S_LEN * K2];
__device__ __nv_bfloat16 g_B1[(size_t)QKV_N * K2];
__device__ __nv_bfloat16 g_A2[(size_t)S_LEN * K2];
__device__ __nv_bfloat16 g_B2[(size_t)H_DIM * K2];

// ---------------- helpers ---------------------------------------------------
__device__ __forceinline__ uint32_t smem_u32(const void* p) {
    uint32_t a;
    asm("{ .reg .u64 t; cvta.to.shared.u64 t, %1; cvt.u32.u64 %0, t; }" : "=r"(a) : "l"(p));
    return a;
}
__device__ __forceinline__ void cpa16(uint32_t dst, const void* src) {
    asm volatile("cp.async.cg.shared.global [%0], [%1], 16;" :: "r"(dst), "l"(src) : "memory");
}
__device__ __forceinline__ uint32_t swz(uint32_t x) { return x ^ ((x >> 3) & 0x70); }

__device__ __forceinline__ void ldmx4(uint32_t* r, uint32_t addr) {
    asm volatile("ldmatrix.sync.aligned.m8n8.x4.shared.b16 {%0,%1,%2,%3}, [%4];"
        : "=r"(r[0]), "=r"(r[1]), "=r"(r[2]), "=r"(r[3]) : "r"(addr));
}
__device__ __forceinline__ void ldmx4t(uint32_t* r, uint32_t addr) {
    asm volatile("ldmatrix.sync.aligned.m8n8.x4.trans.shared.b16 {%0,%1,%2,%3}, [%4];"
        : "=r"(r[0]), "=r"(r[1]), "=r"(r[2]), "=r"(r[3]) : "r"(addr));
}
__device__ __forceinline__ void mma16816(float* c, const uint32_t* a, uint32_t b0, uint32_t b1) {
    asm volatile("mma.sync.aligned.m16n8k16.row.col.f32.bf16.bf16.f32 "
        "{%0,%1,%2,%3}, {%4,%5,%6,%7}, {%8,%9}, {%0,%1,%2,%3};"
        : "+f"(c[0]), "+f"(c[1]), "+f"(c[2]), "+f"(c[3])
        : "r"(a[0]), "r"(a[1]), "r"(a[2]), "r"(a[3]), "r"(b0), "r"(b1));
}
__device__ __forceinline__ void mma16816h(float* c, const uint32_t* a, uint32_t b0, uint32_t b1) {
    asm volatile("mma.sync.aligned.m16n8k16.row.col.f32.f16.f16.f32 "
        "{%0,%1,%2,%3}, {%4,%5,%6,%7}, {%8,%9}, {%0,%1,%2,%3};"
        : "+f"(c[0]), "+f"(c[1]), "+f"(c[2]), "+f"(c[3])
        : "r"(a[0]), "r"(a[1]), "r"(a[2]), "r"(a[3]), "r"(b0), "r"(b1));
}
__device__ __forceinline__ uint32_t pack_h2(float x, float y) {
    __half2 h = __floats2half2_rn(x, y);
    return *(uint32_t*)&h;
}

// ============================================================================
// bf16x2-layout split conversions: X -> [Xh | Xl]
// ============================================================================
__global__ __launch_bounds__(256) void split_a_kernel(
    const float* __restrict__ X, __nv_bfloat16* __restrict__ A, int M)
{
    int idx = blockIdx.x * 256 + threadIdx.x;
    int total = M * (K_IN / 4);
    if (idx >= total) return;
    int m = idx / (K_IN / 4);
    int k = (idx % (K_IN / 4)) * 4;
    float4 v = ((const float4*)X)[idx];
    __nv_bfloat16 h0 = __float2bfloat16_rn(v.x), h1 = __float2bfloat16_rn(v.y);
    __nv_bfloat16 h2 = __float2bfloat16_rn(v.z), h3 = __float2bfloat16_rn(v.w);
    __nv_bfloat162 H0 = __halves2bfloat162(h0, h1), H1 = __halves2bfloat162(h2, h3);
    __nv_bfloat162 L0 = __halves2bfloat162(
        __float2bfloat16_rn(v.x - __bfloat162float(h0)),
        __float2bfloat16_rn(v.y - __bfloat162float(h1)));
    __nv_bfloat162 L1 = __halves2bfloat162(
        __float2bfloat16_rn(v.z - __bfloat162float(h2)),
        __float2bfloat16_rn(v.w - __bfloat162float(h3)));
    __nv_bfloat16* row = A + (size_t)m * K2;
    *(__nv_bfloat162*)(row + k)            = H0; *(__nv_bfloat162*)(row + k + 2)            = H1;
    *(__nv_bfloat162*)(row + K_IN + k)     = L0; *(__nv_bfloat162*)(row + K_IN + k + 2)     = L1;
}

// W [K_IN, N] row-major -> B [N, K2] bf16 K-major: [Bh | Bl]
__global__ __launch_bounds__(256) void split_bT_kernel(
    const float* __restrict__ W, __nv_bfloat16* __restrict__ B, int N)
{
    __shared__ float tl[32][33];
    int n0 = blockIdx.x * 32, k0 = blockIdx.y * 32;
    int tx = threadIdx.x, ty = threadIdx.y;
#pragma unroll
    for (int i = 0; i < 4; i++)
        tl[ty + i * 8][tx] = W[(size_t)(k0 + ty + i * 8) * N + n0 + tx];
    __syncthreads();
#pragma unroll
    for (int i = 0; i < 4; i++) {
        int n = ty + i * 8;
        float x = tl[tx][n];
        __nv_bfloat16 h = __float2bfloat16_rn(x);
        __nv_bfloat16 l = __float2bfloat16_rn(x - __bfloat162float(h));
        __nv_bfloat16* row = B + (size_t)(n0 + n) * K2 + k0 + tx;
        row[0]    = h;
        row[K_IN] = l;
    }
}

// ============================================================================
// HMMA GEMM, shared-fragment bf16x3: C = Ah·Bh + Al·Bh + Ah·Bl.
// CTA 256x128, chunk = 64 original-K, double-buffered 96KB stages (192KB).
// Per k16 step: 12 ldmx4, 96 mma (was 24/96 in the K3 layout).
// ============================================================================
#define AH_OFF 0
#define AL_OFF 32768
#define BH_OFF 65536
#define BL_OFF 81920
#define STAGE_BYTES 98304
#define SMEM_MM (2 * STAGE_BYTES)
#define NCHUNK_MM (K_IN / 64)   // 64

__global__ __launch_bounds__(256, 1) void mm_bf16_kernel(
    const __nv_bfloat16* __restrict__ Abf, const __nv_bfloat16* __restrict__ Bbf,
    float* __restrict__ C, int N)
{
    extern __shared__ char smc[];
    const uint32_t sb = smem_u32(smc);
    const char* Ab = (const char*)Abf;
    const char* Bb = (const char*)Bbf;
    const int t = threadIdx.x, lane = t & 31, wid = t >> 5;
    const int bm = blockIdx.y << 8;
    const int bn = blockIdx.x << 7;
    const size_t rowB = (size_t)K2 * 2;   // 16384 bytes per row

    const int wm = (wid & 3) << 6;
    const int wn = (wid >> 2) << 6;
    const int lr = ((lane >> 3) & 1) * 8 + (lane & 7);
    const int lk = ((lane >> 4) & 1) * 16;

    float acc[4][8][4];
#pragma unroll
    for (int mt = 0; mt < 4; mt++)
#pragma unroll
        for (int nt = 0; nt < 8; nt++)
#pragma unroll
            for (int e = 0; e < 4; e++) acc[mt][nt][e] = 0.f;

    auto loadChunk = [&](int c, uint32_t stg) {
        const int kB = c * 128;
#pragma unroll
        for (int j = 0; j < 8; j++) {          // Ah 32KB
            int idx = t + j * 256; int r = idx >> 3, cc = idx & 7;
            cpa16(stg + AH_OFF + swz(r * 128 + cc * 16),
                  Ab + (size_t)(bm + r) * rowB + kB + cc * 16);
        }
#pragma unroll
        for (int j = 0; j < 8; j++) {          // Al 32KB
            int idx = t + j * 256; int r = idx >> 3, cc = idx & 7;
            cpa16(stg + AL_OFF + swz(r * 128 + cc * 16),
                  Ab + (size_t)(bm + r) * rowB + 8192 + kB + cc * 16);
        }
#pragma unroll
        for (int j = 0; j < 4; j++) {          // Bh 16KB
            int idx = t + j * 256; int r = idx >> 3, cc = idx & 7;
            cpa16(stg + BH_OFF + swz(r * 128 + cc * 16),
                  Bb + (size_t)(bn + r) * rowB + kB + cc * 16);
        }
#pragma unroll
        for (int j = 0; j < 4; j++) {          // Bl 16KB
            int idx = t + j * 256; int r = idx >> 3, cc = idx & 7;
            cpa16(stg + BL_OFF + swz(r * 128 + cc * 16),
                  Bb + (size_t)(bn + r) * rowB + 8192 + kB + cc * 16);
        }
    };

    loadChunk(0, sb);
    asm volatile("cp.async.commit_group;" ::: "memory");

    for (int i = 0; i < NCHUNK_MM; i++) {
        asm volatile("cp.async.wait_group 0;" ::: "memory");
        __syncthreads();

        if (i + 1 < NCHUNK_MM)
            loadChunk(i + 1, sb + ((i + 1) & 1) * STAGE_BYTES);
        asm volatile("cp.async.commit_group;" ::: "memory");

        const uint32_t stg = sb + (i & 1) * STAGE_BYTES;
#pragma unroll
        for (int ks = 0; ks < 4; ks++) {
            const int kOff = ks * 32 + lk;
            uint32_t rah[4][4], rbh[4][4];
#pragma unroll
            for (int mt = 0; mt < 4; mt++)
                ldmx4(rah[mt], stg + AH_OFF + swz((wm + mt * 16 + lr) * 128 + kOff));
#pragma unroll
            for (int ng = 0; ng < 4; ng++)
                ldmx4(rbh[ng], stg + BH_OFF + swz((wn + ng * 16 + lr) * 128 + kOff));
#pragma unroll
            for (int mt = 0; mt < 4; mt++)
#pragma unroll
                for (int ng = 0; ng < 4; ng++) {
                    mma16816(acc[mt][ng * 2],     rah[mt], rbh[ng][0], rbh[ng][2]);
                    mma16816(acc[mt][ng * 2 + 1], rah[mt], rbh[ng][1], rbh[ng][3]);
                }
            // Al x Bh (reuse rbh)
            {
                uint32_t ral[4][4];
#pragma unroll
                for (int mt = 0; mt < 4; mt++)
                    ldmx4(ral[mt], stg + AL_OFF + swz((wm + mt * 16 + lr) * 128 + kOff));
#pragma unroll
                for (int mt = 0; mt < 4; mt++)
#pragma unroll
                    for (int ng = 0; ng < 4; ng++) {
                        mma16816(acc[mt][ng * 2],     ral[mt], rbh[ng][0], rbh[ng][2]);
                        mma16816(acc[mt][ng * 2 + 1], ral[mt], rbh[ng][1], rbh[ng][3]);
                    }
            }
            // Ah x Bl (reuse rah)
            {
                uint32_t rbl[4][4];
#pragma unroll
                for (int ng = 0; ng < 4; ng++)
                    ldmx4(rbl[ng], stg + BL_OFF + swz((wn + ng * 16 + lr) * 128 + kOff));
#pragma unroll
                for (int mt = 0; mt < 4; mt++)
#pragma unroll
                    for (int ng = 0; ng < 4; ng++) {
                        mma16816(acc[mt][ng * 2],     rah[mt], rbl[ng][0], rbl[ng][2]);
                        mma16816(acc[mt][ng * 2 + 1], rah[mt], rbl[ng][1], rbl[ng][3]);
                    }
            }
        }
    }

#pragma unroll
    for (int mt = 0; mt < 4; mt++) {
#pragma unroll
        for (int nt = 0; nt < 8; nt++) {
            int row = bm + wm + mt * 16 + (lane >> 2);
            int col = bn + wn + nt * 8 + (lane & 3) * 2;
            *(float2*)(C + (size_t)row * N + col)       = make_float2(acc[mt][nt][0], acc[mt][nt][1]);
            *(float2*)(C + (size_t)(row + 8) * N + col) = make_float2(acc[mt][nt][2], acc[mt][nt][3]);
        }
    }
}

// ============================================================================
// RoPE (unchanged)
// ============================================================================
__global__ void rope_table_kernel(const int* __restrict__ positions)
{
    int idx = blockIdx.x * blockDim.x + threadIdx.x;
    if (idx >= S_LEN * 64) return;
    int s = idx >> 6, i = idx & 63;
    double inv = pow(10000.0, -((double)i) / 64.0);
    double f   = (double)positions[s] * inv;
    g_cos[idx] = (float)cos(f);
    g_sin[idx] = (float)sin(f);
}

__global__ __launch_bounds__(256) void rope_apply_kernel()
{
    int s = blockIdx.x;
    float* base = g_qkv + (size_t)s * QKV_N;
    for (int idx = threadIdx.x; idx < 40 * 64; idx += 256) {
        int hh = idx >> 6, i = idx & 63;
        int off = (hh < 32) ? hh * 128 : 4096 + (hh - 32) * 128;
        float c  = g_cos[(s << 6) + i];
        float sn = g_sin[(s << 6) + i];
        float a = base[off + i];
        float b = base[off + 64 + i];
        base[off + i]      = a * c - b * sn;
        base[off + 64 + i] = b * c + a * sn;
    }
}

// ============================================================================
// Flash attention, P = 1 + E identity + exact masked-tile M·Vl correction
// (unchanged from R9 except epilogue writes the [Ah|Al] K2 layout).
// ============================================================================
#define ATTN_SMEM 51712
#define RS_PART   49152
#define RS_FINAL  51200

__global__ __launch_bounds__(128, 3) void attn_mma_kernel()
{
    extern __shared__ char smA[];
    const uint32_t sb = smem_u32(smA);
    const uint32_t sQ = sb, sK = sb + 16384, sVh = sb + 32768;

    const int t = threadIdx.x, lane = t & 31, w = t >> 5;
    const int q0 = blockIdx.x << 6;
    const int h  = blockIdx.y;
    const int kvh = h >> 2;
    const float* qb = g_qkv + h * 128;
    const float* kb = g_qkv + 4096 + kvh * 128;
    const float* vb = g_qkv + 5120 + kvh * 128;
    const float scale = 0.08838834764831845f;

    for (int idx = t; idx < 2048; idx += 128) {
        int r = idx >> 5, d4 = idx & 31;
        float4 v = *(const float4*)(qb + (size_t)(q0 + r) * QKV_N + d4 * 4);
        int hf = d4 >> 4, dpr = (d4 & 15) * 4;
        uint2 u;
        u.x = pack_h2(v.x, v.y);
        u.y = pack_h2(v.z, v.w);
        *(uint2*)(smA + hf * 8192 + swz(r * 128 + dpr * 2)) = u;
    }

    const int lr = ((lane >> 3) & 1) * 8 + (lane & 7);
    const int lc = (lane >> 4) * 16;
    const int r0 = lane >> 2;
    const int c2 = (lane & 3) * 2;

    float l_i[2] = {0.f, 0.f};
    float of[16][4];
#pragma unroll
    for (int dd = 0; dd < 16; dd++)
#pragma unroll
        for (int e = 0; e < 4; e++) of[dd][e] = 0.f;

    int lo = q0 - (WINSZ - 1);
    if (lo < 0) lo = 0;
    lo &= ~63;

    const int qi0 = q0 + w * 16 + r0;
    const int qi1 = qi0 + 8;

    for (int j0 = lo; j0 < q0 + 64; j0 += 64) {
        const bool hasMask = (j0 == q0) || (q0 + 63 - j0 >= WINSZ);

        __syncthreads();
        for (int idx = t; idx < 2048; idx += 128) {
            int r = idx >> 5, d4 = idx & 31;
            float4 v = *(const float4*)(kb + (size_t)(j0 + r) * QKV_N + d4 * 4);
            int hf = d4 >> 4, dpr = (d4 & 15) * 4;
            uint2 u;
            u.x = pack_h2(v.x, v.y);
            u.y = pack_h2(v.z, v.w);
            *(uint2*)(smA + 16384 + hf * 8192 + swz(r * 128 + dpr * 2)) = u;
        }
        {
            float prs0 = 0.f, prs1 = 0.f, prs2 = 0.f, prs3 = 0.f;
            const int d4 = t & 31;
            const int hf = d4 >> 4, dpr = (d4 & 15) * 4;
#pragma unroll
            for (int i = 0; i < 16; i++) {
                int j = (t >> 5) + i * 4;
                float4 v = *(const float4*)(vb + (size_t)(j0 + j) * QKV_N + d4 * 4);
                uint2 uh;
                uh.x = pack_h2(v.x, v.y);
                uh.y = pack_h2(v.z, v.w);
                *(uint2*)(smA + 32768 + (hf << 13) + swz(j * 128 + dpr * 2)) = uh;
                prs0 += v.x; prs1 += v.y; prs2 += v.z; prs3 += v.w;
            }
            *(float4*)(smA + RS_PART + ((t >> 5) * 128 + d4 * 4) * 4) =
                make_float4(prs0, prs1, prs2, prs3);
        }
        __syncthreads();
        {
            const float* sP = (const float*)(smA + RS_PART);
            float rsum = sP[t] + sP[128 + t] + sP[256 + t] + sP[384 + t];
            *(float*)(smA + RS_FINAL + t * 4) = rsum;
        }
        __syncthreads();

        float sf[8][4];
#pragma unroll
        for (int f = 0; f < 8; f++)
#pragma unroll
            for (int e = 0; e < 4; e++) sf[f][e] = 0.f;

#pragma unroll
        for (int ks = 0; ks < 8; ks++) {
            const int hf = ks >> 2;
            const int kOff = (ks & 3) * 32 + lc;
            uint32_t ra[4];
            ldmx4(ra, sQ + hf * 8192 + swz((w * 16 + lr) * 128 + kOff));
#pragma unroll
            for (int jb = 0; jb < 4; jb++) {
                uint32_t rb[4];
                ldmx4(rb, sK + hf * 8192 + swz((jb * 16 + lr) * 128 + kOff));
                mma16816h(sf[jb * 2],     ra, rb[0], rb[2]);
                mma16816h(sf[jb * 2 + 1], ra, rb[1], rb[3]);
            }
        }

        if (hasMask) {
            __syncthreads();
            for (int idx = t; idx < 2048; idx += 128) {
                int j = idx >> 5, d4 = idx & 31;
                float4 v = *(const float4*)(vb + (size_t)(j0 + j) * QKV_N + d4 * 4);
                int hf = d4 >> 4, dpr = (d4 & 15) * 4;
                __half h0 = __float2half_rn(v.x), h1 = __float2half_rn(v.y);
                __half h2 = __float2half_rn(v.z), h3 = __float2half_rn(v.w);
                uint2 ul;
                ul.x = pack_h2(v.x - __half2float(h0), v.y - __half2float(h1));
                ul.y = pack_h2(v.z - __half2float(h2), v.w - __half2float(h3));
                *(uint2*)(smA + 16384 + (hf << 13) + swz(j * 128 + dpr * 2)) = ul;
            }
            __syncthreads();
        }

        float rs0 = 0.f, rs1 = 0.f;
#pragma unroll
        for (int f = 0; f < 8; f++) {
            int kj = j0 + f * 8 + c2;
#pragma unroll
            for (int e = 0; e < 2; e++) {
                int kje = kj + e;
                bool ok0 = (kje <= qi0) && ((qi0 - kje) < WINSZ);
                bool ok1 = (kje <= qi1) && ((qi1 - kje) < WINSZ);
                float e0 = ok0 ? (__expf(sf[f][e] * scale)     - 1.f) : -1.f;
                float e1 = ok1 ? (__expf(sf[f][e + 2] * scale) - 1.f) : -1.f;
                sf[f][e] = e0; sf[f][e + 2] = e1;
                rs0 += e0; rs1 += e1;
            }
        }
        rs0 += __shfl_xor_sync(0xffffffffu, rs0, 1);
        rs0 += __shfl_xor_sync(0xffffffffu, rs0, 2);
        rs1 += __shfl_xor_sync(0xffffffffu, rs1, 1);
        rs1 += __shfl_xor_sync(0xffffffffu, rs1, 2);
        l_i[0] += 64.f + rs0;
        l_i[1] += 64.f + rs1;

        const float* rsF = (const float*)(smA + RS_FINAL);
#pragma unroll
        for (int dd = 0; dd < 16; dd++) {
            float ra = rsF[dd * 8 + c2];
            float rb = rsF[dd * 8 + c2 + 1];
            of[dd][0] += ra; of[dd][1] += rb;
            of[dd][2] += ra; of[dd][3] += rb;
        }
#pragma unroll
        for (int kk = 0; kk < 4; kk++) {
            uint32_t aE[4], aM[4];
#pragma unroll
            for (int g = 0; g < 2; g++) {
                int f = kk * 2 + g;
                aE[g * 2]     = pack_h2(sf[f][0], sf[f][1]);
                aE[g * 2 + 1] = pack_h2(sf[f][2], sf[f][3]);
                if (hasMask) {
                    int kj = j0 + f * 8 + c2;
                    float m00 = ((kj     <= qi0) && ((qi0 - kj)     < WINSZ)) ? 0.f : -1.f;
                    float m01 = ((kj + 1 <= qi0) && ((qi0 - kj - 1) < WINSZ)) ? 0.f : -1.f;
                    float m10 = ((kj     <= qi1) && ((qi1 - kj)     < WINSZ)) ? 0.f : -1.f;
                    float m11 = ((kj + 1 <= qi1) && ((qi1 - kj - 1) < WINSZ)) ? 0.f : -1.f;
                    aM[g * 2]     = pack_h2(m00, m01);
                    aM[g * 2 + 1] = pack_h2(m10, m11);
                }
            }
#pragma unroll
            for (int db = 0; db < 8; db++) {
                const int hf = db >> 2;
                const int dloc = (db & 3) * 16;
                uint32_t addr = (hf << 13) + swz((kk * 16 + lr) * 128 + dloc * 2 + lc);
                uint32_t vh[4];
                ldmx4t(vh, sVh + addr);
                mma16816h(of[db * 2],     aE, vh[0], vh[1]);
                mma16816h(of[db * 2 + 1], aE, vh[2], vh[3]);
                if (hasMask) {
                    uint32_t vl[4];
                    ldmx4t(vl, sK + addr);
                    mma16816h(of[db * 2],     aM, vl[0], vl[1]);
                    mma16816h(of[db * 2 + 1], aM, vl[2], vl[3]);
                }
            }
        }
    }

    // ---- epilogue: normalize + [Ah|Al] split directly into A2 (K2 layout) ----
    float inv0 = 1.f / l_i[0], inv1 = 1.f / l_i[1];
    __nv_bfloat16* rowA0 = g_A2 + (size_t)(q0 + w * 16 + r0) * K2 + h * 128;
    __nv_bfloat16* rowA1 = g_A2 + (size_t)(q0 + w * 16 + r0 + 8) * K2 + h * 128;
#pragma unroll
    for (int dd = 0; dd < 16; dd++) {
        int d = dd * 8 + c2;
        float x0 = of[dd][0] * inv0, x1 = of[dd][1] * inv0;
        float y0 = of[dd][2] * inv1, y1 = of[dd][3] * inv1;
        __nv_bfloat16 xh0 = __float2bfloat16_rn(x0), xh1 = __float2bfloat16_rn(x1);
        __nv_bfloat16 yh0 = __float2bfloat16_rn(y0), yh1 = __float2bfloat16_rn(y1);
        __nv_bfloat162 XH = __halves2bfloat162(xh0, xh1);
        __nv_bfloat162 YH = __halves2bfloat162(yh0, yh1);
        __nv_bfloat162 XL = __halves2bfloat162(
            __float2bfloat16_rn(x0 - __bfloat162float(xh0)),
            __float2bfloat16_rn(x1 - __bfloat162float(xh1)));
        __nv_bfloat162 YL = __halves2bfloat162(
            __float2bfloat16_rn(y0 - __bfloat162float(yh0)),
            __float2bfloat16_rn(y1 - __bfloat162float(yh1)));
        *(__nv_bfloat162*)(rowA0 + d)        = XH;
        *(__nv_bfloat162*)(rowA0 + d + K_IN) = XL;
        *(__nv_bfloat162*)(rowA1 + d)        = YH;
        *(__nv_bfloat162*)(rowA1 + d + K_IN) = YL;
    }
}

// ============================================================================
// launch
// ============================================================================
extern "C" void kernel_launch(void* const* d_in, const int* in_sizes, int n_in,
                              void* d_out, int out_size)
{
    const int*   positions = (const int*)d_in[0];
    const float* hidden    = (const float*)d_in[1];
    const float* w_qkv     = (const float*)d_in[2];
    const float* w_o       = (const float*)d_in[3];
    float*       out       = (float*)d_out;

    float* qkv;
    __nv_bfloat16 *A1, *B1, *A2, *B2;
    cudaGetSymbolAddress((void**)&qkv, g_qkv);
    cudaGetSymbolAddress((void**)&A1, g_A1);
    cudaGetSymbolAddress((void**)&B1, g_B1);
    cudaGetSymbolAddress((void**)&A2, g_A2);
    cudaGetSymbolAddress((void**)&B2, g_B2);

    cudaFuncSetAttribute(mm_bf16_kernel, cudaFuncAttributeMaxDynamicSharedMemorySize, SMEM_MM);
    cudaFuncSetAttribute(attn_mma_kernel, cudaFuncAttributeMaxDynamicSharedMemorySize, ATTN_SMEM);

    rope_table_kernel<<<(S_LEN * 64 + 255) / 256, 256>>>(positions);

    split_a_kernel<<<(S_LEN * (K_IN / 4) + 255) / 256, 256>>>(hidden, A1, S_LEN);
    split_bT_kernel<<<dim3(QKV_N / 32, K_IN / 32), dim3(32, 8)>>>(w_qkv, B1, QKV_N);
    split_bT_kernel<<<dim3(H_DIM / 32, K_IN / 32), dim3(32, 8)>>>(w_o, B2, H_DIM);

    mm_bf16_kernel<<<dim3(QKV_N / 128, S_LEN / 256), 256, SMEM_MM>>>(A1, B1, qkv, QKV_N);

    rope_apply_kernel<<<S_LEN, 256>>>();

    attn_mma_kernel<<<dim3(S_LEN / 64, NHQ), 128, ATTN_SMEM>>>();

    mm_bf16_kernel<<<dim3(H_DIM / 128, S_LEN / 256), 256, SMEM_MM>>>(A2, B2, out, H_DIM);
}